// round 12
// baseline (speedup 1.0000x reference)
#include <cuda_runtime.h>

#define NL 128   // rows of lines tables
#define CL 32    // embedding width
#define HD 128   // hidden dim
#define NFLAG (3 * NL)
#define SAMPLE_CH 128               // sampler: 16 warps x 8 chunks
#define ROWB  32                    // row blocks (4 rows each)
#define FILLB 148                   // fill blocks (1 per SM)
#define TPB  512
#define GRID (1 + ROWB + FILLB)     // 181

// Persistent device scratch (allocations forbidden). g_rcnt nets to zero per
// launch (32 x +1 from row blocks, one -32 from the sampler) => deterministic
// graph replays.
__device__ unsigned g_rcnt;   // row-block arrival counter (fallback gate only)

__global__ __launch_bounds__(TPB) void k_fused(
    const float4* __restrict__ c4, int n128,
    const float*  __restrict__ cflat, int nfloats,
    const float*  __restrict__ lines0, const float* __restrict__ lines1,
    const float*  __restrict__ lines2, const float* __restrict__ w1,
    const float*  __restrict__ b1, const float* __restrict__ w2,
    const float*  __restrict__ b2, float* __restrict__ out, int nout)
{
    const int tid  = threadIdx.x;
    const int lane = tid & 31;
    const int wid  = tid >> 5;

    // ==================================================================
    // FILL TRACK (blocks >= 1+ROWB): c0 + fill out[NL..nout), exit.
    // ==================================================================
    if (blockIdx.x >= 1 + ROWB) {
        float v = 0.f;
        #pragma unroll
        for (int i = 0; i < 4; i++) {
            float bb = __ldg(&b1[lane + 32 * i]);
            float ww = __ldg(&w2[lane + 32 * i]);
            v = fmaf(fmaxf(bb, 0.f), ww, v);
        }
        #pragma unroll
        for (int o = 16; o; o >>= 1) v += __shfl_xor_sync(~0u, v, o);
        const float c0 = v + __ldg(&b2[0]);

        const int gid = (blockIdx.x - 1 - ROWB) * TPB + tid;
        const int gsz = FILLB * TPB;
        const float4 cv = make_float4(c0, c0, c0, c0);
        float4* out4 = (float4*)out;
        const int n4 = nout >> 2;

        int q = (NL / 4) + gid;
        #pragma unroll 4
        for (; q + 3 * gsz < n4; q += 4 * gsz) {
            out4[q]           = cv;
            out4[q + gsz]     = cv;
            out4[q + 2 * gsz] = cv;
            out4[q + 3 * gsz] = cv;
        }
        for (; q < n4; q += gsz) out4[q] = cv;
        for (int s = (n4 << 2) + gid; s < nout; s += gsz)
            if (s >= NL) out[s] = c0;
        return;
    }

    // ==================================================================
    // ROW TRACK (blocks 1..ROWB): 4 combo-7 rows each (one per 128-thread
    // group), optimistic direct write; fire-and-forget RED arrival.
    // ==================================================================
    if (blockIdx.x >= 1) {
        __shared__ float s_feats[4][CL];
        __shared__ float s_red[16];
        const int rb = blockIdx.x - 1;
        const int g  = tid >> 7;            // group 0..3 -> row
        const int ht = tid & 127;           // thread within group
        const int r  = rb * 4 + g;

        float lx = 0.f, ly = 0.f, lz = 0.f;
        if (ht < CL) {
            lx = __ldg(&lines0[r * CL + ht]);
            ly = __ldg(&lines1[r * CL + ht]);
            lz = __ldg(&lines2[r * CL + ht]);
        }
        float4 wreg[8];
        {
            const float4* w4 = (const float4*)(w1 + ht * CL);
            #pragma unroll
            for (int q = 0; q < 8; q++) wreg[q] = __ldg(&w4[q]);
        }
        const float b1v = __ldg(&b1[ht]);
        const float w2v = __ldg(&w2[ht]);
        const float b2v = __ldg(&b2[0]);

        if (ht < CL) {
            float f1 = lx + ly + lz;
            float f2 = (lx * ly + lx * lz + ly * lz) / 0.4f;
            float f3 = lx * ly * lz / 0.16000000000000003f;
            s_feats[g][ht] = f1 + f2 + f3;
        }
        __syncthreads();

        float acc = b1v;
        #pragma unroll
        for (int q = 0; q < 8; q++) {
            acc = fmaf(wreg[q].x, s_feats[g][q * 4 + 0], acc);
            acc = fmaf(wreg[q].y, s_feats[g][q * 4 + 1], acc);
            acc = fmaf(wreg[q].z, s_feats[g][q * 4 + 2], acc);
            acc = fmaf(wreg[q].w, s_feats[g][q * 4 + 3], acc);
        }
        float term = fmaxf(acc, 0.f) * w2v;
        #pragma unroll
        for (int o = 16; o; o >>= 1) term += __shfl_down_sync(~0u, term, o);
        if (lane == 0) s_red[wid] = term;
        __syncthreads();
        if (ht == 0 && r < nout)
            out[r] = s_red[4 * g] + s_red[4 * g + 1] +
                     s_red[4 * g + 2] + s_red[4 * g + 3] + b2v;

        __threadfence();
        if (tid == 0) atomicAdd(&g_rcnt, 1u);   // return unused -> RED
        return;
    }

    // ==================================================================
    // SAMPLER TRACK (block 0, 16 warps): scan 128 chunks (8/warp, batched
    // 4) into shared flags; saturation check is LOCAL — zero global sync
    // on the fast path.
    // ==================================================================
    __shared__ unsigned sflag[NFLAG];
    __shared__ float    s_feats1[CL];
    __shared__ float    s_red1[16];
    __shared__ int      s_ok[16];
    __shared__ int      s_res;

    const int nchunks = n128 / 96;

    // Axis mapping: warp reads 96 consecutive float4s per chunk; flat idx
    // f = 4*(c*96+lane+32s)+i, axis(f) = (lane+2s+i)%3 = (p+j)%3 with
    // p = lane%3, compile-time j. k = round((v+2)*32) ==
    // __float2int_rn(fmaf(v,32,64)) bit-exactly (pow-2 scale commutes with
    // fp32 rounding; round-half-even in both).
    const int p = lane % 3;
    int e1 = p + 1; if (e1 == 3) e1 = 0;
    int e2 = e1 + 1; if (e2 == 3) e2 = 0;
    const unsigned B0 = (unsigned)p  * NL;
    const unsigned B1 = (unsigned)e1 * NL;
    const unsigned B2 = (unsigned)e2 * NL;

#define PROC(v, BB) {                                                \
        float t_ = fmaf((v), 32.0f, 64.0f);                          \
        int k_ = __float2int_rn(t_);                                 \
        if ((unsigned)k_ < (unsigned)NL) sflag[(BB) + k_] = 1u; }

#define PROC_CHUNK(f0, f1, f2)                                       \
        PROC(f0.x, B0) PROC(f0.y, B1) PROC(f0.z, B2) PROC(f0.w, B0)  \
        PROC(f1.x, B2) PROC(f1.y, B0) PROC(f1.z, B1) PROC(f1.w, B2)  \
        PROC(f2.x, B1) PROC(f2.y, B2) PROC(f2.z, B0) PROC(f2.w, B1)

    for (int i = tid; i < NFLAG; i += TPB) sflag[i] = 0u;
    __syncthreads();

    // Warp wid scans chunks [wid*8, wid*8+8) in 2 batches of 4: 12 LDG.128
    // in flight per batch; only 2 dependent DRAM windows per warp.
    {
        const int cbase = wid * 8;
        #pragma unroll
        for (int b = 0; b < 2; b++) {
            float4 f[4][3];
            #pragma unroll
            for (int c = 0; c < 4; c++) {
                const int ch = cbase + b * 4 + c;
                if (ch < nchunks) {
                    const int ba = ch * 96 + lane;
                    f[c][0] = c4[ba];
                    f[c][1] = c4[ba + 32];
                    f[c][2] = c4[ba + 64];
                } else {
                    // out-of-range -> values mapping outside [0,128)
                    f[c][0] = f[c][1] = f[c][2] = make_float4(1e9f, 1e9f, 1e9f, 1e9f);
                }
            }
            #pragma unroll
            for (int c = 0; c < 4; c++) { PROC_CHUNK(f[c][0], f[c][1], f[c][2]) }
        }
    }
    __syncthreads();

    // Local saturation check: warp w (w<12) ballots flag word w.
    {
        int ok = 1;
        if (wid < 12) {
            unsigned w0 = __ballot_sync(~0u, sflag[wid * 32 + lane] != 0u);
            ok = (w0 == 0xFFFFFFFFu);
        }
        if (lane == 0) s_ok[wid] = ok;
    }
    __syncthreads();
    if (tid == 0) {
        int c = 1;
        #pragma unroll
        for (int i = 0; i < 12; i++) c &= s_ok[i];
        s_res = c;
    }
    __syncthreads();

    if (s_res) {
        // Fast path (always, for this data): flags saturated => combo 7
        // everywhere => the optimistic row writes are already correct and
        // the remaining input provably cannot change the output (flags are
        // monotone). Commutative counter reset; no wait.
        if (tid == 0) atomicAdd(&g_rcnt, (unsigned)-ROWB);
        return;
    }

    // ------------------------------------------------------------------
    // Fallback (correct for arbitrary inputs; P ~ 1e-9 here): wait for all
    // optimistic row writes, scan the entire unsampled remainder, then
    // recompute all rows with their true combos.
    // ------------------------------------------------------------------
    if (tid == 0) {
        unsigned c;
        do {
            asm volatile("ld.global.cg.u32 %0, [%1];" : "=r"(c) : "l"(&g_rcnt));
            if (c >= (unsigned)ROWB) break;
            __nanosleep(128);
        } while (true);
    }
    __syncthreads();

    for (int c = SAMPLE_CH + wid; c < nchunks; c += 16) {
        const int ba = c * 96 + lane;
        float4 f0 = c4[ba];
        float4 f1 = c4[ba + 32];
        float4 f2 = c4[ba + 64];
        PROC_CHUNK(f0, f1, f2)
    }
    for (int q = nchunks * 96 + tid; q < n128; q += TPB) {
        float4 f = c4[q];
        float vv[4] = {f.x, f.y, f.z, f.w};
        #pragma unroll
        for (int i = 0; i < 4; i++) {
            int d = (int)(((q << 2) + i) % 3);
            int k_ = __float2int_rn(fmaf(vv[i], 32.0f, 64.0f));
            if ((unsigned)k_ < (unsigned)NL) sflag[d * NL + k_] = 1u;
        }
    }
    for (int q = (n128 << 2) + tid; q < nfloats; q += TPB) {
        int d = (int)(q % 3);
        int k_ = __float2int_rn(fmaf(cflat[q], 32.0f, 64.0f));
        if ((unsigned)k_ < (unsigned)NL) sflag[d * NL + k_] = 1u;
    }
    __syncthreads();

    for (int rr = 0; rr < NL && rr < nout; rr++) {
        float fx = sflag[rr]          ? 1.f : 0.f;
        float fy = sflag[NL + rr]     ? 1.f : 0.f;
        float fz = sflag[2 * NL + rr] ? 1.f : 0.f;
        if (tid < CL) {
            float x = __ldg(&lines0[rr * CL + tid]) * fx;
            float y = __ldg(&lines1[rr * CL + tid]) * fy;
            float z = __ldg(&lines2[rr * CL + tid]) * fz;
            float f1 = x + y + z;
            float f2 = (x * y + x * z + y * z) / 0.4f;
            float f3 = x * y * z / 0.16000000000000003f;
            s_feats1[tid] = f1 + f2 + f3;
        }
        __syncthreads();
        float term = 0.f;
        if (tid < HD) {
            float acc = __ldg(&b1[tid]);
            const float4* w4 = (const float4*)(w1 + tid * CL);
            #pragma unroll
            for (int q = 0; q < CL / 4; q++) {
                float4 wv = __ldg(&w4[q]);
                acc = fmaf(wv.x, s_feats1[q * 4 + 0], acc);
                acc = fmaf(wv.y, s_feats1[q * 4 + 1], acc);
                acc = fmaf(wv.z, s_feats1[q * 4 + 2], acc);
                acc = fmaf(wv.w, s_feats1[q * 4 + 3], acc);
            }
            term = fmaxf(acc, 0.f) * __ldg(&w2[tid]);
        }
        #pragma unroll
        for (int o = 16; o; o >>= 1) term += __shfl_down_sync(~0u, term, o);
        __syncthreads();
        if (tid < HD && lane == 0) s_red1[wid] = term;
        __syncthreads();
        if (tid == 0)
            out[rr] = s_red1[0] + s_red1[1] + s_red1[2] + s_red1[3] + __ldg(&b2[0]);
        __syncthreads();
    }
#undef PROC_CHUNK
#undef PROC

    // Reset for next replay (all ROWB arrivals observed above).
    if (tid == 0) atomicAdd(&g_rcnt, (unsigned)-ROWB);
}

// ---------------------------------------------------------------------------
extern "C" void kernel_launch(void* const* d_in, const int* in_sizes, int n_in,
                              void* d_out, int out_size) {
    const float* coords = (const float*)d_in[0];
    const float* lines0 = (const float*)d_in[1];
    const float* lines1 = (const float*)d_in[2];
    const float* lines2 = (const float*)d_in[3];
    const float* w1     = (const float*)d_in[4];
    const float* b1     = (const float*)d_in[5];
    const float* w2     = (const float*)d_in[6];
    const float* b2     = (const float*)d_in[7];
    float* out = (float*)d_out;

    const int nfloats = in_sizes[0];
    const int n128 = nfloats >> 2;

    k_fused<<<GRID, TPB>>>((const float4*)coords, n128, coords, nfloats,
                           lines0, lines1, lines2, w1, b1, w2, b2,
                           out, out_size);
}

// round 13
// speedup vs baseline: 1.0923x; 1.0923x over previous
#include <cuda_runtime.h>

#define NL 128   // rows of lines tables
#define CL 32    // embedding width
#define HD 128   // hidden dim
#define NFLAG (3 * NL)
#define SAMPB 4                     // sampler blocks
#define CH_PER_BLK 64               // 8 warps x 8 chunks
#define SAMPLE_CH (SAMPB * CH_PER_BLK)  // 256 chunks (1.5 MB)
#define ROWB  64                    // row blocks (2 rows each)
#define FILLB 148                   // fill blocks (1 per SM)
#define TPB  256
#define GRID (SAMPB + ROWB + FILLB) // 216

// Persistent device scratch (allocations forbidden). All counters net to zero
// per launch; maskbits reset by the checker => deterministic graph replays.
__device__ unsigned g_maskbits[12];   // packed flags: [axis*4 + word32]
__device__ unsigned g_scnt;           // sampler arrival counter
__device__ unsigned g_rcnt;           // row-block arrival counter (fallback gate)

__global__ __launch_bounds__(TPB) void k_fused(
    const float4* __restrict__ c4, int n128,
    const float*  __restrict__ cflat, int nfloats,
    const float*  __restrict__ lines0, const float* __restrict__ lines1,
    const float*  __restrict__ lines2, const float* __restrict__ w1,
    const float*  __restrict__ b1, const float* __restrict__ w2,
    const float*  __restrict__ b2, float* __restrict__ out, int nout)
{
    const int tid  = threadIdx.x;
    const int lane = tid & 31;
    const int wid  = tid >> 5;

    // ==================================================================
    // FILL TRACK (blocks >= SAMPB+ROWB): c0 + fill out[NL..nout), exit.
    // (Identical to the 8.67us round-11 fill track.)
    // ==================================================================
    if (blockIdx.x >= SAMPB + ROWB) {
        float v = 0.f;
        #pragma unroll
        for (int i = 0; i < 4; i++) {
            float bb = __ldg(&b1[lane + 32 * i]);
            float ww = __ldg(&w2[lane + 32 * i]);
            v = fmaf(fmaxf(bb, 0.f), ww, v);
        }
        #pragma unroll
        for (int o = 16; o; o >>= 1) v += __shfl_xor_sync(~0u, v, o);
        const float c0 = v + __ldg(&b2[0]);

        const int gid = (blockIdx.x - SAMPB - ROWB) * TPB + tid;
        const int gsz = FILLB * TPB;
        const float4 cv = make_float4(c0, c0, c0, c0);
        float4* out4 = (float4*)out;
        const int n4 = nout >> 2;

        int q = (NL / 4) + gid;
        #pragma unroll 4
        for (; q + 3 * gsz < n4; q += 4 * gsz) {
            out4[q]           = cv;
            out4[q + gsz]     = cv;
            out4[q + 2 * gsz] = cv;
            out4[q + 3 * gsz] = cv;
        }
        for (; q < n4; q += gsz) out4[q] = cv;
        for (int s = (n4 << 2) + gid; s < nout; s += gsz)
            if (s >= NL) out[s] = c0;
        return;
    }

    // ==================================================================
    // ROW TRACK (blocks SAMPB..SAMPB+ROWB-1): 2 combo-7 rows, optimistic
    // direct write; fire-and-forget RED arrival (fallback gate only).
    // (Identical to the 8.67us round-11 row track.)
    // ==================================================================
    if (blockIdx.x >= SAMPB) {
        __shared__ float s_feats[2][CL];
        __shared__ float s_red[8];
        const int rb   = blockIdx.x - SAMPB;
        const int half = tid >> 7;
        const int ht   = tid & 127;
        const int r    = rb * 2 + half;

        float lx = 0.f, ly = 0.f, lz = 0.f;
        if (ht < CL) {
            lx = __ldg(&lines0[r * CL + ht]);
            ly = __ldg(&lines1[r * CL + ht]);
            lz = __ldg(&lines2[r * CL + ht]);
        }
        float4 wreg[8];
        {
            const float4* w4 = (const float4*)(w1 + ht * CL);
            #pragma unroll
            for (int q = 0; q < 8; q++) wreg[q] = __ldg(&w4[q]);
        }
        const float b1v = __ldg(&b1[ht]);
        const float w2v = __ldg(&w2[ht]);
        const float b2v = __ldg(&b2[0]);

        if (ht < CL) {
            float f1 = lx + ly + lz;
            float f2 = (lx * ly + lx * lz + ly * lz) / 0.4f;
            float f3 = lx * ly * lz / 0.16000000000000003f;
            s_feats[half][ht] = f1 + f2 + f3;
        }
        __syncthreads();

        float acc = b1v;
        #pragma unroll
        for (int q = 0; q < 8; q++) {
            acc = fmaf(wreg[q].x, s_feats[half][q * 4 + 0], acc);
            acc = fmaf(wreg[q].y, s_feats[half][q * 4 + 1], acc);
            acc = fmaf(wreg[q].z, s_feats[half][q * 4 + 2], acc);
            acc = fmaf(wreg[q].w, s_feats[half][q * 4 + 3], acc);
        }
        float term = fmaxf(acc, 0.f) * w2v;
        #pragma unroll
        for (int o = 16; o; o >>= 1) term += __shfl_down_sync(~0u, term, o);
        if (lane == 0) s_red[wid] = term;
        __syncthreads();
        if (tid == 0 && rb * 2 < nout)
            out[rb * 2] = s_red[0] + s_red[1] + s_red[2] + s_red[3] + b2v;
        if (tid == 128 && r < nout)
            out[r] = s_red[4] + s_red[5] + s_red[6] + s_red[7] + b2v;

        __threadfence();
        if (tid == 0) atomicAdd(&g_rcnt, 1u);   // return unused -> RED
        return;
    }

    // ==================================================================
    // SAMPLER TRACK (blocks 0..3): 8 chunks/warp in 2 batches of 4 ->
    // shared flags -> 4-deep atomic merge. Last arriver checks union.
    // ==================================================================
    __shared__ unsigned sflag[NFLAG];
    __shared__ float    s_feats1[CL];
    __shared__ float    s_red1[8];
    __shared__ int      s_last;
    __shared__ unsigned s_m12[12];

    const int nchunks = n128 / 96;

    // Axis mapping: warp reads 96 consecutive float4s per chunk; flat idx
    // f = 4*(c*96+lane+32s)+i, axis(f) = (lane+2s+i)%3 = (p+j)%3 with
    // p = lane%3, compile-time j. k = round((v+2)*32) ==
    // __float2int_rn(fmaf(v,32,64)) bit-exactly (pow-2 scale commutes with
    // fp32 rounding; round-half-even in both).
    const int p = lane % 3;
    int e1 = p + 1; if (e1 == 3) e1 = 0;
    int e2 = e1 + 1; if (e2 == 3) e2 = 0;
    const unsigned B0 = (unsigned)p  * NL;
    const unsigned B1 = (unsigned)e1 * NL;
    const unsigned B2 = (unsigned)e2 * NL;

#define PROC(v, BB) {                                                \
        float t_ = fmaf((v), 32.0f, 64.0f);                          \
        int k_ = __float2int_rn(t_);                                 \
        if ((unsigned)k_ < (unsigned)NL) sflag[(BB) + k_] = 1u; }

#define PROC_CHUNK(f0, f1, f2)                                       \
        PROC(f0.x, B0) PROC(f0.y, B1) PROC(f0.z, B2) PROC(f0.w, B0)  \
        PROC(f1.x, B2) PROC(f1.y, B0) PROC(f1.z, B1) PROC(f1.w, B2)  \
        PROC(f2.x, B1) PROC(f2.y, B2) PROC(f2.z, B0) PROC(f2.w, B1)

    for (int i = tid; i < NFLAG; i += TPB) sflag[i] = 0u;
    __syncthreads();

    // Warp wid scans chunks [base, base+8) in 2 batches of 4: 12 LDG.128 in
    // flight per batch; 2 dependent DRAM windows per warp.
    {
        const int cbase = (blockIdx.x * 8 + wid) * 8;
        #pragma unroll
        for (int b = 0; b < 2; b++) {
            float4 f[4][3];
            #pragma unroll
            for (int c = 0; c < 4; c++) {
                const int ch = cbase + b * 4 + c;
                if (ch < nchunks) {
                    const int ba = ch * 96 + lane;
                    f[c][0] = c4[ba];
                    f[c][1] = c4[ba + 32];
                    f[c][2] = c4[ba + 64];
                } else {
                    // out-of-range -> values mapping outside [0,128)
                    f[c][0] = f[c][1] = f[c][2] = make_float4(1e9f, 1e9f, 1e9f, 1e9f);
                }
            }
            #pragma unroll
            for (int c = 0; c < 4; c++) { PROC_CHUNK(f[c][0], f[c][1], f[c][2]) }
        }
    }
    __syncthreads();

    // Merge: ballot-pack 12 words, atomicOr to global (4-way contention).
    {
        unsigned bal = __ballot_sync(~0u, sflag[wid * 32 + lane] != 0u);
        if (lane == 0 && bal) atomicOr(&g_maskbits[wid], bal);
        if (wid < 4) {
            int j = wid + 8;
            unsigned bl2 = __ballot_sync(~0u, sflag[j * 32 + lane] != 0u);
            if (lane == 0 && bl2) atomicOr(&g_maskbits[j], bl2);
        }
    }
    __threadfence();
    if (tid == 0) {
        unsigned t = atomicAdd(&g_scnt, 1u);
        s_last = (t == (unsigned)(SAMPB - 1)) ? 1 : 0;
    }
    __syncthreads();
    if (!s_last) return;

    // ---- checker (last sampler): union saturation ----
    __threadfence();
    if (tid == 0) {
        int c = 1;
        #pragma unroll
        for (int i = 0; i < 12; i++)
            c &= (__ldcg(&g_maskbits[i]) == 0xFFFFFFFFu);
        s_last = c + 1;   // 2 = saturated, 1 = fallback
    }
    __syncthreads();

    if (s_last == 2) {
        // Fast path (always, for this data): flags saturated => combo 7
        // everywhere => optimistic row writes already correct; the unread
        // input provably cannot change the output (flags are monotone).
        if (tid < 12) g_maskbits[tid] = 0u;      // safe: all sampler ORs done
        if (tid == 0) {
            atomicAdd(&g_scnt, (unsigned)-SAMPB);  // net 0 per launch
            atomicAdd(&g_rcnt, (unsigned)-ROWB);
        }
        return;
    }

    // ------------------------------------------------------------------
    // Fallback (correct for arbitrary inputs; P ~ e^-55 here): wait for
    // all optimistic row writes, scan the unsampled remainder, merge with
    // the union, recompute all rows with true combos, reset state.
    // ------------------------------------------------------------------
    if (tid == 0) {
        unsigned c;
        do {
            asm volatile("ld.global.cg.u32 %0, [%1];" : "=r"(c) : "l"(&g_rcnt));
            if (c >= (unsigned)ROWB) break;
            __nanosleep(128);
        } while (true);
    }
    __syncthreads();

    for (int c = SAMPLE_CH + wid; c < nchunks; c += 8) {
        const int ba = c * 96 + lane;
        float4 f0 = c4[ba];
        float4 f1 = c4[ba + 32];
        float4 f2 = c4[ba + 64];
        PROC_CHUNK(f0, f1, f2)
    }
    for (int q = nchunks * 96 + tid; q < n128; q += TPB) {
        float4 f = c4[q];
        float vv[4] = {f.x, f.y, f.z, f.w};
        #pragma unroll
        for (int i = 0; i < 4; i++) {
            int d = (int)(((q << 2) + i) % 3);
            int k_ = __float2int_rn(fmaf(vv[i], 32.0f, 64.0f));
            if ((unsigned)k_ < (unsigned)NL) sflag[d * NL + k_] = 1u;
        }
    }
    for (int q = (n128 << 2) + tid; q < nfloats; q += TPB) {
        int d = (int)(q % 3);
        int k_ = __float2int_rn(fmaf(cflat[q], 32.0f, 64.0f));
        if ((unsigned)k_ < (unsigned)NL) sflag[d * NL + k_] = 1u;
    }
    __syncthreads();
    {
        unsigned bal = __ballot_sync(~0u, sflag[wid * 32 + lane] != 0u);
        if (lane == 0) s_m12[wid] = bal | __ldcg(&g_maskbits[wid]);
        if (wid < 4) {
            int j = wid + 8;
            unsigned bl2 = __ballot_sync(~0u, sflag[j * 32 + lane] != 0u);
            if (lane == 0) s_m12[j] = bl2 | __ldcg(&g_maskbits[j]);
        }
    }
    __syncthreads();
    for (int rr = 0; rr < NL && rr < nout; rr++) {
        unsigned fx = (s_m12[(rr >> 5)]     >> (rr & 31)) & 1u;
        unsigned fy = (s_m12[4 + (rr >> 5)] >> (rr & 31)) & 1u;
        unsigned fz = (s_m12[8 + (rr >> 5)] >> (rr & 31)) & 1u;
        if (tid < CL) {
            float x = __ldg(&lines0[rr * CL + tid]) * (float)fx;
            float y = __ldg(&lines1[rr * CL + tid]) * (float)fy;
            float z = __ldg(&lines2[rr * CL + tid]) * (float)fz;
            float f1 = x + y + z;
            float f2 = (x * y + x * z + y * z) / 0.4f;
            float f3 = x * y * z / 0.16000000000000003f;
            s_feats1[tid] = f1 + f2 + f3;
        }
        __syncthreads();
        float term = 0.f;
        if (tid < HD) {
            float acc = __ldg(&b1[tid]);
            const float4* w4 = (const float4*)(w1 + tid * CL);
            #pragma unroll
            for (int q = 0; q < CL / 4; q++) {
                float4 wv = __ldg(&w4[q]);
                acc = fmaf(wv.x, s_feats1[q * 4 + 0], acc);
                acc = fmaf(wv.y, s_feats1[q * 4 + 1], acc);
                acc = fmaf(wv.z, s_feats1[q * 4 + 2], acc);
                acc = fmaf(wv.w, s_feats1[q * 4 + 3], acc);
            }
            term = fmaxf(acc, 0.f) * __ldg(&w2[tid]);
        }
        #pragma unroll
        for (int o = 16; o; o >>= 1) term += __shfl_down_sync(~0u, term, o);
        __syncthreads();
        if (tid < HD && lane == 0) s_red1[wid] = term;
        __syncthreads();
        if (tid == 0)
            out[rr] = s_red1[0] + s_red1[1] + s_red1[2] + s_red1[3] + __ldg(&b2[0]);
        __syncthreads();
    }
#undef PROC_CHUNK
#undef PROC

    // Reset for next replay.
    __syncthreads();
    if (tid < 12) g_maskbits[tid] = 0u;
    if (tid == 0) { atomicExch(&g_rcnt, 0u); atomicExch(&g_scnt, 0u); }
}

// ---------------------------------------------------------------------------
extern "C" void kernel_launch(void* const* d_in, const int* in_sizes, int n_in,
                              void* d_out, int out_size) {
    const float* coords = (const float*)d_in[0];
    const float* lines0 = (const float*)d_in[1];
    const float* lines1 = (const float*)d_in[2];
    const float* lines2 = (const float*)d_in[3];
    const float* w1     = (const float*)d_in[4];
    const float* b1     = (const float*)d_in[5];
    const float* w2     = (const float*)d_in[6];
    const float* b2     = (const float*)d_in[7];
    float* out = (float*)d_out;

    const int nfloats = in_sizes[0];
    const int n128 = nfloats >> 2;

    k_fused<<<GRID, TPB>>>((const float4*)coords, n128, coords, nfloats,
                           lines0, lines1, lines2, w1, b1, w2, b2,
                           out, out_size);
}